// round 12
// baseline (speedup 1.0000x reference)
#include <cuda_runtime.h>
#include <cuda_bf16.h>
#include <math.h>
#include <stdint.h>

// ---------------- problem constants ----------------
#define NB 4
#define HF 63
#define P  3969
#define RP 4096            // rows padded per image
#define KP 80              // 75 feats + 2 coord feats + 3 zero pad
#define NI 32
#define NJH 2              // j halves
#define NJT 16             // j tiles per half
#define IN_H 67
#define CS  0.31622776601683794f   // sqrt(0.1)
#define L2E 1.4426950408889634f

// ---------------- scratch ----------------
__device__ __nv_bfloat16 g_hi[(size_t)2 * NB * RP * KP];
__device__ float    g_r[2 * NB * RP];
__device__ unsigned g_dmin[NB * RP];
__device__ float    g_rowsum[NB * RP];
__device__ float    g_acc[NB];

// ---------------- helpers ----------------
__device__ __forceinline__ uint32_t smem_u32(const void* p) {
    uint32_t a;
    asm("{ .reg .u64 t; cvta.to.shared.u64 t, %1; cvt.u32.u64 %0, t; }" : "=r"(a) : "l"(p));
    return a;
}
__device__ __forceinline__ void cp16(uint32_t dst, const void* src) {
    asm volatile("cp.async.cg.shared.global [%0], [%1], 16;" :: "r"(dst), "l"(src));
}
#define CP_COMMIT() asm volatile("cp.async.commit_group;" ::: "memory")
#define CP_WAIT0()  asm volatile("cp.async.wait_group 0;" ::: "memory")

__device__ __forceinline__ void ldsm4(uint32_t* r, uint32_t addr) {
    asm volatile("ldmatrix.sync.aligned.m8n8.x4.shared.b16 {%0,%1,%2,%3}, [%4];"
        : "=r"(r[0]), "=r"(r[1]), "=r"(r[2]), "=r"(r[3]) : "r"(addr));
}
__device__ __forceinline__ void mma16816(float* d, const uint32_t* a, uint32_t b0, uint32_t b1) {
    asm volatile("mma.sync.aligned.m16n8k16.row.col.f32.bf16.bf16.f32 "
        "{%0,%1,%2,%3},{%4,%5,%6,%7},{%8,%9},{%0,%1,%2,%3};"
        : "+f"(d[0]), "+f"(d[1]), "+f"(d[2]), "+f"(d[3])
        : "r"(a[0]), "r"(a[1]), "r"(a[2]), "r"(a[3]), "r"(b0), "r"(b1));
}
__device__ __forceinline__ float ex2f(float x) {
    float y; asm("ex2.approx.f32 %0, %1;" : "=f"(y) : "f"(x)); return y;
}
// monotone float<->uint for atomicMin over possibly-negative floats
__device__ __forceinline__ unsigned fenc(float f) {
    int b = __float_as_int(f);
    return (unsigned)(b >= 0 ? (b | 0x80000000) : ~b);
}
__device__ __forceinline__ float fdec(unsigned u) {
    int b = (u & 0x80000000u) ? (int)(u ^ 0x80000000u) : ~(int)u;
    return __int_as_float(b);
}

// ---------------- prep: features + row norms + clears, one kernel ----------------
__global__ __launch_bounds__(256) void featrsq_kernel(const float* __restrict__ outp,
                                                      const float* __restrict__ targ) {
    int gid = blockIdx.x * blockDim.x + threadIdx.x;
    if (gid < NB * RP) { g_dmin[gid] = 0xFFFFFFFFu; g_rowsum[gid] = 0.0f; }
    if (gid < NB) g_acc[gid] = 0.0f;

    int gw = gid >> 5;
    int l  = threadIdx.x & 31;
    if (gw >= 2 * NB * RP) return;
    int row   = gw % RP;
    int n     = (gw / RP) % NB;
    int which = gw / (RP * NB);

    __nv_bfloat16* dst = g_hi + (size_t)gw * KP;
    const float* src = which ? targ : outp;
    int y = row / HF, x = row - y * HF;
    bool valid = (row < P);

    float sum = 0.0f;
    #pragma unroll
    for (int k = l; k < KP; k += 32) {
        float v = 0.0f;
        if (valid) {
            if (k < 75) {
                int c = k / 25, t = k - c * 25, dy = t / 5, dx = t - dy * 5;
                v = src[((n * 3 + c) * IN_H + y + dy) * IN_H + x + dx] - 0.5f;
            } else if (k == 75) v = CS * (float)y * (1.0f / 62.0f);
            else if (k == 76)   v = CS * (float)x * (1.0f / 62.0f);
        }
        dst[k] = __float2bfloat16(v);
        sum = fmaf(v, v, sum);
    }
    #pragma unroll
    for (int off = 16; off >= 1; off >>= 1)
        sum += __shfl_xor_sync(0xffffffffu, sum, off);
    if (l == 0) {
        if (which == 1 && row >= P) sum = 1e9f;   // T pad rows: huge dist -> exp underflows to 0
        g_r[gw] = sum;
    }
}

// ---------------- two-pass fused GEMM kernels ----------------
#define TS     176                 // smem row stride (bytes), ldmatrix conflict-free
#define TILE_B (128 * TS)          // 22528
#define SM_RT  0                   // 2 x 128 f
#define SM_RED 1024                // 128 u32: pass1 encoded min / pass2 float partial sums
#define SM_M   1536                // 128 f (pass2)
#define SM_B2  2048                // 128 f (pass2)
#define SM_AH  4096
#define SM_B0  (SM_AH + TILE_B)
#define SMEM_BYTES (SM_B0 + 2 * TILE_B)   // 71680 (70 KB); 2 CTAs/SM = 140 KB

__device__ __forceinline__ void load_B_async(uint32_t smB,
                                             const __nv_bfloat16* __restrict__ hi, int tid) {
    for (int t = tid; t < 1280; t += 256) {
        int row = t / 10, c = t - row * 10;
        cp16(smB + row * TS + c * 16, hi + row * KP + c * 8);
    }
}

template <int PASS>
__global__ __launch_bounds__(256, 2) void pass_kernel() {
    extern __shared__ char sm[];
    uint32_t smb = smem_u32(sm);
    int tid = threadIdx.x;
    int w = tid >> 5, l = tid & 31;
    int n  = blockIdx.z;
    int i0 = blockIdx.x * 128;
    int jh = blockIdx.y;
    int wm = w >> 1, wn = w & 1;        // 4 x 2 warp grid, warp tile 32 x 64

    float*    rT_s  = (float*)(sm + SM_RT);
    unsigned* red_s = (unsigned*)(sm + SM_RED);
    float*    sum_s = (float*)(sm + SM_RED);
    float*    m_s   = (float*)(sm + SM_M);
    float*    b_s   = (float*)(sm + SM_B2);

    // ---- load A_hi tile (once) + per-pass row state ----
    const __nv_bfloat16* Ahi = g_hi + ((size_t)n * RP + i0) * KP;
    for (int t = tid; t < 1280; t += 256) {
        int row = t / 10, c = t - row * 10;
        *(uint4*)(sm + SM_AH + row * TS + c * 16) = *(const uint4*)(Ahi + row * KP + c * 8);
    }
    if (tid < 128) {
        if (PASS == 0) {
            red_s[tid] = 0xFFFFFFFFu;
        } else {
            sum_s[tid] = 0.0f;
            float smin = fdec(g_dmin[n * RP + i0 + tid]);
            float dmin = g_r[n * RP + i0 + tid] + smin;   // first half of g_r = rI
            float m = -L2E / (0.5f * (dmin + 1e-5f));
            m_s[tid] = m;
            b_s[tid] = -smin * m;
        }
    }
    __syncthreads();

    // ---- per-lane geometry ----
    int qr = l >> 2;
    int qc = (l & 3) * 2;
    int lrow = (l & 7) + ((l >> 3) & 1) * 8;
    int lcol = (l >> 4) * 16;
    int aoff = (wm * 32 + lrow) * TS + lcol;
    int boff = (wn * 64 + lrow) * TS + lcol;

    const __nv_bfloat16* Bhi0 = g_hi + ((size_t)(NB + n) * RP + jh * (NJT * 128)) * KP;
    const float* rTg = g_r + (NB + n) * RP + jh * (NJT * 128);

    float rmin[2][2] = {{1e30f, 1e30f}, {1e30f, 1e30f}};
    float rsum[2][2] = {{0.f, 0.f}, {0.f, 0.f}};
    float mrow[2][2], brow[2][2];
    if (PASS == 1) {
        #pragma unroll
        for (int mt = 0; mt < 2; ++mt)
            #pragma unroll
            for (int h = 0; h < 2; ++h) {
                int row = wm * 32 + mt * 16 + h * 8 + qr;
                mrow[mt][h] = m_s[row];
                brow[mt][h] = b_s[row];
            }
    }

    // preload j=0
    load_B_async(smb + SM_B0, Bhi0, tid);
    CP_COMMIT();
    if (tid < 128) rT_s[tid] = rTg[tid];

    for (int j = 0; j < NJT; ++j) {
        int cur = j & 1;
        CP_WAIT0();
        __syncthreads();               // B[cur] ready; everyone done reading B[cur^1]

        if (j + 1 < NJT) {
            load_B_async(smb + SM_B0 + (cur ^ 1) * TILE_B,
                         Bhi0 + (size_t)(j + 1) * 128 * KP, tid);
            CP_COMMIT();
            if (tid < 128) rT_s[(cur ^ 1) * 128 + tid] = rTg[(j + 1) * 128 + tid];
        }

        // ---- GEMM: pure bf16 hh, 32x64 warp tile ----
        float acc[2][8][4];
        #pragma unroll
        for (int mt = 0; mt < 2; ++mt)
            #pragma unroll
            for (int nt = 0; nt < 8; ++nt)
                #pragma unroll
                for (int q = 0; q < 4; ++q) acc[mt][nt][q] = 0.0f;

        uint32_t Bcur = smb + SM_B0 + cur * TILE_B;
        #pragma unroll
        for (int kk = 0; kk < 5; ++kk) {
            uint32_t AH0[4], AH1[4], BF[4][4];
            ldsm4(AH0, smb + SM_AH + aoff + kk * 32);
            ldsm4(AH1, smb + SM_AH + aoff + 16 * TS + kk * 32);
            #pragma unroll
            for (int f = 0; f < 4; ++f)
                ldsm4(BF[f], Bcur + boff + f * 16 * TS + kk * 32);
            #pragma unroll
            for (int f = 0; f < 4; ++f) {
                mma16816(acc[0][2 * f],     AH0, BF[f][0], BF[f][2]);
                mma16816(acc[0][2 * f + 1], AH0, BF[f][1], BF[f][3]);
                mma16816(acc[1][2 * f],     AH1, BF[f][0], BF[f][2]);
                mma16816(acc[1][2 * f + 1], AH1, BF[f][1], BF[f][3]);
            }
        }

        // ---- epilogue: s = rT - 2*dot ----
        #pragma unroll
        for (int nt = 0; nt < 8; ++nt) {
            float2 rtp = *(const float2*)&rT_s[cur * 128 + wn * 64 + nt * 8 + qc];
            #pragma unroll
            for (int mt = 0; mt < 2; ++mt)
                #pragma unroll
                for (int h = 0; h < 2; ++h) {
                    float s0 = fmaf(-2.0f, acc[mt][nt][2 * h],     rtp.x);
                    float s1 = fmaf(-2.0f, acc[mt][nt][2 * h + 1], rtp.y);
                    if (PASS == 0) {
                        rmin[mt][h] = fminf(rmin[mt][h], fminf(s0, s1));
                    } else {
                        rsum[mt][h] += ex2f(fmaf(s0, mrow[mt][h], brow[mt][h]));
                        rsum[mt][h] += ex2f(fmaf(s1, mrow[mt][h], brow[mt][h]));
                    }
                }
        }
    }

    // ---- per-row reductions: quad -> shared -> global ----
    if (PASS == 0) {
        #pragma unroll
        for (int mt = 0; mt < 2; ++mt)
            #pragma unroll
            for (int h = 0; h < 2; ++h) {
                float v = rmin[mt][h];
                v = fminf(v, __shfl_xor_sync(0xffffffffu, v, 1));
                v = fminf(v, __shfl_xor_sync(0xffffffffu, v, 2));
                if ((l & 3) == 0)
                    atomicMin(&red_s[wm * 32 + mt * 16 + qr + h * 8], fenc(v));
            }
        __syncthreads();
        if (tid < 128) atomicMin(&g_dmin[n * RP + i0 + tid], red_s[tid]);
    } else {
        #pragma unroll
        for (int mt = 0; mt < 2; ++mt)
            #pragma unroll
            for (int h = 0; h < 2; ++h) {
                float v = rsum[mt][h];
                v += __shfl_xor_sync(0xffffffffu, v, 1);
                v += __shfl_xor_sync(0xffffffffu, v, 2);
                if ((l & 3) == 0)
                    atomicAdd(&sum_s[wm * 32 + mt * 16 + qr + h * 8], v);
            }
        __syncthreads();
        if (tid < 128) atomicAdd(&g_rowsum[n * RP + i0 + tid], sum_s[tid]);
    }
}

// ---------------- finalize: per-image sum of k_max ----------------
__global__ __launch_bounds__(256) void finalize_kernel() {
    int n = blockIdx.x;
    float s = 0.0f;
    for (int i = threadIdx.x; i < P; i += 256)
        s += 1.0f / g_rowsum[n * RP + i];
    #pragma unroll
    for (int off = 16; off >= 1; off >>= 1)
        s += __shfl_xor_sync(0xffffffffu, s, off);
    __shared__ float red[8];
    if ((threadIdx.x & 31) == 0) red[threadIdx.x >> 5] = s;
    __syncthreads();
    if (threadIdx.x == 0) {
        float t = 0.0f;
        #pragma unroll
        for (int q = 0; q < 8; ++q) t += red[q];
        g_acc[n] = t;
    }
}

__global__ void final_kernel(float* out) {
    float L = 0.0f;
    #pragma unroll
    for (int n = 0; n < NB; ++n)
        L += -logf(g_acc[n] * (1.0f / (float)P));
    out[0] = L;
}

// ---------------- launch ----------------
extern "C" void kernel_launch(void* const* d_in, const int* in_sizes, int n_in,
                              void* d_out, int out_size) {
    const float* outp = (const float*)d_in[0];
    const float* targ = (const float*)d_in[1];
    float* out = (float*)d_out;

    cudaFuncSetAttribute(pass_kernel<0>, cudaFuncAttributeMaxDynamicSharedMemorySize, SMEM_BYTES);
    cudaFuncSetAttribute(pass_kernel<1>, cudaFuncAttributeMaxDynamicSharedMemorySize, SMEM_BYTES);

    featrsq_kernel<<<(2 * NB * RP) / 8, 256>>>(outp, targ);
    dim3 g(NI, NJH, NB);
    pass_kernel<0><<<g, 256, SMEM_BYTES>>>();
    pass_kernel<1><<<g, 256, SMEM_BYTES>>>();
    finalize_kernel<<<NB, 256>>>();
    final_kernel<<<1, 1>>>(out);
}

// round 13
// speedup vs baseline: 1.0445x; 1.0445x over previous
#include <cuda_runtime.h>
#include <cuda_bf16.h>
#include <cuda_fp16.h>
#include <math.h>
#include <stdint.h>

// ---------------- problem constants ----------------
#define NB 4
#define HF 63
#define P  3969
#define RP 4096            // rows padded per image
#define KP 80              // 75 feats + 2 coord feats + 3 zero pad
#define NI 32
#define NJH 2              // j halves
#define NJT 16             // j tiles per half
#define IN_H 67
#define CS  0.31622776601683794f   // sqrt(0.1)
#define L2E 1.4426950408889634f

// ---------------- scratch ----------------
__device__ __nv_bfloat16 g_hi[(size_t)2 * NB * RP * KP];
__device__ float    g_r[2 * NB * RP];
__device__ unsigned g_dmin[NB * RP];
__device__ float    g_rowsum[NB * RP];
__device__ float    g_acc[NB];

// ---------------- helpers ----------------
__device__ __forceinline__ uint32_t smem_u32(const void* p) {
    uint32_t a;
    asm("{ .reg .u64 t; cvta.to.shared.u64 t, %1; cvt.u32.u64 %0, t; }" : "=r"(a) : "l"(p));
    return a;
}
__device__ __forceinline__ void cp16(uint32_t dst, const void* src) {
    asm volatile("cp.async.cg.shared.global [%0], [%1], 16;" :: "r"(dst), "l"(src));
}
#define CP_COMMIT() asm volatile("cp.async.commit_group;" ::: "memory")
#define CP_WAIT0()  asm volatile("cp.async.wait_group 0;" ::: "memory")

__device__ __forceinline__ void ldsm4(uint32_t* r, uint32_t addr) {
    asm volatile("ldmatrix.sync.aligned.m8n8.x4.shared.b16 {%0,%1,%2,%3}, [%4];"
        : "=r"(r[0]), "=r"(r[1]), "=r"(r[2]), "=r"(r[3]) : "r"(addr));
}
__device__ __forceinline__ void mma16816(float* d, const uint32_t* a, uint32_t b0, uint32_t b1) {
    asm volatile("mma.sync.aligned.m16n8k16.row.col.f32.bf16.bf16.f32 "
        "{%0,%1,%2,%3},{%4,%5,%6,%7},{%8,%9},{%0,%1,%2,%3};"
        : "+f"(d[0]), "+f"(d[1]), "+f"(d[2]), "+f"(d[3])
        : "r"(a[0]), "r"(a[1]), "r"(a[2]), "r"(a[3]), "r"(b0), "r"(b1));
}
__device__ __forceinline__ uint32_t pack_f16x2(float lo, float hi) {
    uint32_t u;
    asm("cvt.rn.f16x2.f32 %0, %1, %2;" : "=r"(u) : "f"(hi), "f"(lo));
    return u;
}
__device__ __forceinline__ uint32_t ex2_f16x2(uint32_t h) {
    uint32_t e;
    asm("ex2.approx.f16x2 %0, %1;" : "=r"(e) : "r"(h));
    return e;
}
__device__ __forceinline__ float rcpf(float x) {
    float y; asm("rcp.approx.f32 %0, %1;" : "=f"(y) : "f"(x)); return y;
}
// monotone float<->uint for atomicMin over possibly-negative floats
__device__ __forceinline__ unsigned fenc(float f) {
    int b = __float_as_int(f);
    return (unsigned)(b >= 0 ? (b | 0x80000000) : ~b);
}
__device__ __forceinline__ float fdec(unsigned u) {
    int b = (u & 0x80000000u) ? (int)(u ^ 0x80000000u) : ~(int)u;
    return __int_as_float(b);
}

// ---------------- prep: features + row norms + clears, one kernel ----------------
__global__ __launch_bounds__(256) void featrsq_kernel(const float* __restrict__ outp,
                                                      const float* __restrict__ targ) {
    int gid = blockIdx.x * blockDim.x + threadIdx.x;
    if (gid < NB * RP) { g_dmin[gid] = 0xFFFFFFFFu; g_rowsum[gid] = 0.0f; }
    if (gid < NB) g_acc[gid] = 0.0f;

    int gw = gid >> 5;
    int l  = threadIdx.x & 31;
    if (gw >= 2 * NB * RP) return;
    int row   = gw % RP;
    int n     = (gw / RP) % NB;
    int which = gw / (RP * NB);

    __nv_bfloat16* dst = g_hi + (size_t)gw * KP;
    const float* src = which ? targ : outp;
    int y = row / HF, x = row - y * HF;
    bool valid = (row < P);

    float sum = 0.0f;
    #pragma unroll
    for (int k = l; k < KP; k += 32) {
        float v = 0.0f;
        if (valid) {
            if (k < 75) {
                int c = k / 25, t = k - c * 25, dy = t / 5, dx = t - dy * 5;
                v = src[((n * 3 + c) * IN_H + y + dy) * IN_H + x + dx] - 0.5f;
            } else if (k == 75) v = CS * (float)y * (1.0f / 62.0f);
            else if (k == 76)   v = CS * (float)x * (1.0f / 62.0f);
        }
        dst[k] = __float2bfloat16(v);
        sum = fmaf(v, v, sum);
    }
    #pragma unroll
    for (int off = 16; off >= 1; off >>= 1)
        sum += __shfl_xor_sync(0xffffffffu, sum, off);
    if (l == 0) {
        if (which == 1 && row >= P) sum = 1e9f;   // T pad rows: huge dist -> exp underflows to 0
        g_r[gw] = sum;
    }
}

// ---------------- two-pass fused GEMM kernels ----------------
#define TS     176                 // smem row stride (bytes), ldmatrix conflict-free
#define TILE_B (128 * TS)          // 22528
#define SM_RT  0                   // 2 x 128 f
#define SM_RED 1024                // 128 u32: pass1 encoded min / pass2 float partial sums
#define SM_M   1536                // 128 f (pass2)
#define SM_B2  2048                // 128 f (pass2)
#define SM_AH  4096
#define SM_B0  (SM_AH + TILE_B)
#define SMEM_BYTES (SM_B0 + 2 * TILE_B)   // 71680 (70 KB); 2 CTAs/SM = 140 KB

__device__ __forceinline__ void load_B_async(uint32_t smB,
                                             const __nv_bfloat16* __restrict__ hi, int tid) {
    for (int t = tid; t < 1280; t += 256) {
        int row = t / 10, c = t - row * 10;
        cp16(smB + row * TS + c * 16, hi + row * KP + c * 8);
    }
}

template <int PASS>
__global__ __launch_bounds__(256, 2) void pass_kernel() {
    extern __shared__ char sm[];
    uint32_t smb = smem_u32(sm);
    int tid = threadIdx.x;
    int w = tid >> 5, l = tid & 31;
    int n  = blockIdx.z;
    int i0 = blockIdx.x * 128;
    int jh = blockIdx.y;
    int wm = w >> 1, wn = w & 1;        // 4 x 2 warp grid, warp tile 32 x 64

    float*    rT_s  = (float*)(sm + SM_RT);
    unsigned* red_s = (unsigned*)(sm + SM_RED);
    float*    sum_s = (float*)(sm + SM_RED);
    float*    m_s   = (float*)(sm + SM_M);
    float*    b_s   = (float*)(sm + SM_B2);

    // ---- load A_hi tile (once) + per-pass row state ----
    const __nv_bfloat16* Ahi = g_hi + ((size_t)n * RP + i0) * KP;
    for (int t = tid; t < 1280; t += 256) {
        int row = t / 10, c = t - row * 10;
        *(uint4*)(sm + SM_AH + row * TS + c * 16) = *(const uint4*)(Ahi + row * KP + c * 8);
    }
    if (tid < 128) {
        if (PASS == 0) {
            red_s[tid] = 0xFFFFFFFFu;
        } else {
            sum_s[tid] = 0.0f;
            float smin = fdec(g_dmin[n * RP + i0 + tid]);
            float dmin = g_r[n * RP + i0 + tid] + smin;   // first half of g_r = rI
            float m = -L2E / (0.5f * (dmin + 1e-5f));
            m_s[tid] = m;
            b_s[tid] = -smin * m;
        }
    }
    __syncthreads();

    // ---- per-lane geometry ----
    int qr = l >> 2;
    int qc = (l & 3) * 2;
    int lrow = (l & 7) + ((l >> 3) & 1) * 8;
    int lcol = (l >> 4) * 16;
    int aoff = (wm * 32 + lrow) * TS + lcol;
    int boff = (wn * 64 + lrow) * TS + lcol;

    const __nv_bfloat16* Bhi0 = g_hi + ((size_t)(NB + n) * RP + jh * (NJT * 128)) * KP;
    const float* rTg = g_r + (NB + n) * RP + jh * (NJT * 128);

    float rmin[2][2] = {{1e30f, 1e30f}, {1e30f, 1e30f}};
    float rsum[2][2] = {{0.f, 0.f}, {0.f, 0.f}};
    float mrow[2][2], brow[2][2];
    if (PASS == 1) {
        #pragma unroll
        for (int mt = 0; mt < 2; ++mt)
            #pragma unroll
            for (int h = 0; h < 2; ++h) {
                int row = wm * 32 + mt * 16 + h * 8 + qr;
                mrow[mt][h] = m_s[row];
                brow[mt][h] = b_s[row];
            }
    }

    // preload j=0
    load_B_async(smb + SM_B0, Bhi0, tid);
    CP_COMMIT();
    if (tid < 128) rT_s[tid] = rTg[tid];

    for (int j = 0; j < NJT; ++j) {
        int cur = j & 1;
        CP_WAIT0();
        __syncthreads();               // B[cur] ready; everyone done reading B[cur^1]

        if (j + 1 < NJT) {
            load_B_async(smb + SM_B0 + (cur ^ 1) * TILE_B,
                         Bhi0 + (size_t)(j + 1) * 128 * KP, tid);
            CP_COMMIT();
            if (tid < 128) rT_s[(cur ^ 1) * 128 + tid] = rTg[(j + 1) * 128 + tid];
        }

        // ---- GEMM: pure bf16 hh, 32x64 warp tile ----
        float acc[2][8][4];
        #pragma unroll
        for (int mt = 0; mt < 2; ++mt)
            #pragma unroll
            for (int nt = 0; nt < 8; ++nt)
                #pragma unroll
                for (int q = 0; q < 4; ++q) acc[mt][nt][q] = 0.0f;

        uint32_t Bcur = smb + SM_B0 + cur * TILE_B;
        #pragma unroll
        for (int kk = 0; kk < 5; ++kk) {
            uint32_t AH0[4], AH1[4], BF[4][4];
            ldsm4(AH0, smb + SM_AH + aoff + kk * 32);
            ldsm4(AH1, smb + SM_AH + aoff + 16 * TS + kk * 32);
            #pragma unroll
            for (int f = 0; f < 4; ++f)
                ldsm4(BF[f], Bcur + boff + f * 16 * TS + kk * 32);
            #pragma unroll
            for (int f = 0; f < 4; ++f) {
                mma16816(acc[0][2 * f],     AH0, BF[f][0], BF[f][2]);
                mma16816(acc[0][2 * f + 1], AH0, BF[f][1], BF[f][3]);
                mma16816(acc[1][2 * f],     AH1, BF[f][0], BF[f][2]);
                mma16816(acc[1][2 * f + 1], AH1, BF[f][1], BF[f][3]);
            }
        }

        // ---- epilogue: s = rT - 2*dot ----
        #pragma unroll
        for (int nt = 0; nt < 8; ++nt) {
            float2 rtp = *(const float2*)&rT_s[cur * 128 + wn * 64 + nt * 8 + qc];
            #pragma unroll
            for (int mt = 0; mt < 2; ++mt)
                #pragma unroll
                for (int h = 0; h < 2; ++h) {
                    float s0 = fmaf(-2.0f, acc[mt][nt][2 * h],     rtp.x);
                    float s1 = fmaf(-2.0f, acc[mt][nt][2 * h + 1], rtp.y);
                    if (PASS == 0) {
                        rmin[mt][h] = fminf(rmin[mt][h], fminf(s0, s1));
                    } else {
                        float a0 = fmaf(s0, mrow[mt][h], brow[mt][h]);
                        float a1 = fmaf(s1, mrow[mt][h], brow[mt][h]);
                        uint32_t e = ex2_f16x2(pack_f16x2(a0, a1));
                        float2 ef = __half22float2(*(__half2*)&e);
                        rsum[mt][h] += ef.x + ef.y;
                    }
                }
        }
    }

    // ---- per-row reductions: quad -> shared -> global ----
    if (PASS == 0) {
        #pragma unroll
        for (int mt = 0; mt < 2; ++mt)
            #pragma unroll
            for (int h = 0; h < 2; ++h) {
                float v = rmin[mt][h];
                v = fminf(v, __shfl_xor_sync(0xffffffffu, v, 1));
                v = fminf(v, __shfl_xor_sync(0xffffffffu, v, 2));
                if ((l & 3) == 0)
                    atomicMin(&red_s[wm * 32 + mt * 16 + qr + h * 8], fenc(v));
            }
        __syncthreads();
        if (tid < 128) atomicMin(&g_dmin[n * RP + i0 + tid], red_s[tid]);
    } else {
        #pragma unroll
        for (int mt = 0; mt < 2; ++mt)
            #pragma unroll
            for (int h = 0; h < 2; ++h) {
                float v = rsum[mt][h];
                v += __shfl_xor_sync(0xffffffffu, v, 1);
                v += __shfl_xor_sync(0xffffffffu, v, 2);
                if ((l & 3) == 0)
                    atomicAdd(&sum_s[wm * 32 + mt * 16 + qr + h * 8], v);
            }
        __syncthreads();
        if (tid < 128) atomicAdd(&g_rowsum[n * RP + i0 + tid], sum_s[tid]);
    }
}

// ---------------- finalize: per-image sum of k_max (parallel, rcp.approx) ----------------
__global__ __launch_bounds__(256) void finalize_kernel() {
    int n = blockIdx.y;
    int i = blockIdx.x * 256 + threadIdx.x;
    float s = (i < P) ? rcpf(g_rowsum[n * RP + i]) : 0.0f;
    #pragma unroll
    for (int off = 16; off >= 1; off >>= 1)
        s += __shfl_xor_sync(0xffffffffu, s, off);
    __shared__ float red[8];
    if ((threadIdx.x & 31) == 0) red[threadIdx.x >> 5] = s;
    __syncthreads();
    if (threadIdx.x == 0) {
        float t = 0.0f;
        #pragma unroll
        for (int q = 0; q < 8; ++q) t += red[q];
        atomicAdd(&g_acc[n], t);
    }
}

__global__ void final_kernel(float* out) {
    float L = 0.0f;
    #pragma unroll
    for (int n = 0; n < NB; ++n)
        L += -logf(g_acc[n] * (1.0f / (float)P));
    out[0] = L;
}

// ---------------- launch ----------------
extern "C" void kernel_launch(void* const* d_in, const int* in_sizes, int n_in,
                              void* d_out, int out_size) {
    const float* outp = (const float*)d_in[0];
    const float* targ = (const float*)d_in[1];
    float* out = (float*)d_out;

    cudaFuncSetAttribute(pass_kernel<0>, cudaFuncAttributeMaxDynamicSharedMemorySize, SMEM_BYTES);
    cudaFuncSetAttribute(pass_kernel<1>, cudaFuncAttributeMaxDynamicSharedMemorySize, SMEM_BYTES);

    featrsq_kernel<<<(2 * NB * RP) / 8, 256>>>(outp, targ);
    dim3 g(NI, NJH, NB);
    pass_kernel<0><<<g, 256, SMEM_BYTES>>>();
    pass_kernel<1><<<g, 256, SMEM_BYTES>>>();
    finalize_kernel<<<dim3(16, NB), 256>>>();
    final_kernel<<<1, 1>>>(out);
}

// round 14
// speedup vs baseline: 1.0766x; 1.0307x over previous
#include <cuda_runtime.h>
#include <cuda_bf16.h>
#include <cuda_fp16.h>
#include <math.h>
#include <stdint.h>

// ---------------- problem constants ----------------
#define NB 4
#define HF 63
#define P  3969
#define RP 4096            // rows padded per image
#define KP 80              // 75 feats + 2 coord feats + 3 zero pad
#define NI 32
#define NJH 2              // j halves
#define NJT 16             // j tiles per half
#define IN_H 67
#define CS  0.31622776601683794f   // sqrt(0.1)
#define L2E 1.4426950408889634f

// ---------------- scratch ----------------
__device__ __nv_bfloat16 g_hi[(size_t)2 * NB * RP * KP];
__device__ float    g_r[2 * NB * RP];
__device__ unsigned g_dmin[NB * RP];
__device__ float    g_rowsum[NB * RP];
__device__ float    g_acc[NB];

// ---------------- helpers ----------------
__device__ __forceinline__ uint32_t smem_u32(const void* p) {
    uint32_t a;
    asm("{ .reg .u64 t; cvta.to.shared.u64 t, %1; cvt.u32.u64 %0, t; }" : "=r"(a) : "l"(p));
    return a;
}
__device__ __forceinline__ void cp16(uint32_t dst, const void* src) {
    asm volatile("cp.async.cg.shared.global [%0], [%1], 16;" :: "r"(dst), "l"(src));
}
#define CP_COMMIT() asm volatile("cp.async.commit_group;" ::: "memory")
#define CP_WAIT0()  asm volatile("cp.async.wait_group 0;" ::: "memory")

__device__ __forceinline__ void ldsm4(uint32_t* r, uint32_t addr) {
    asm volatile("ldmatrix.sync.aligned.m8n8.x4.shared.b16 {%0,%1,%2,%3}, [%4];"
        : "=r"(r[0]), "=r"(r[1]), "=r"(r[2]), "=r"(r[3]) : "r"(addr));
}
__device__ __forceinline__ void mma16816(float* d, const uint32_t* a, uint32_t b0, uint32_t b1) {
    asm volatile("mma.sync.aligned.m16n8k16.row.col.f32.bf16.bf16.f32 "
        "{%0,%1,%2,%3},{%4,%5,%6,%7},{%8,%9},{%0,%1,%2,%3};"
        : "+f"(d[0]), "+f"(d[1]), "+f"(d[2]), "+f"(d[3])
        : "r"(a[0]), "r"(a[1]), "r"(a[2]), "r"(a[3]), "r"(b0), "r"(b1));
}
__device__ __forceinline__ uint32_t pack_f16x2(float lo, float hi) {
    uint32_t u;
    asm("cvt.rn.f16x2.f32 %0, %1, %2;" : "=r"(u) : "f"(hi), "f"(lo));
    return u;
}
__device__ __forceinline__ uint32_t ex2_f16x2(uint32_t h) {
    uint32_t e;
    asm("ex2.approx.f16x2 %0, %1;" : "=r"(e) : "r"(h));
    return e;
}
__device__ __forceinline__ float rcpf(float x) {
    float y; asm("rcp.approx.f32 %0, %1;" : "=f"(y) : "f"(x)); return y;
}
// monotone float<->uint for atomicMin over possibly-negative floats
__device__ __forceinline__ unsigned fenc(float f) {
    int b = __float_as_int(f);
    return (unsigned)(b >= 0 ? (b | 0x80000000) : ~b);
}
__device__ __forceinline__ float fdec(unsigned u) {
    int b = (u & 0x80000000u) ? (int)(u ^ 0x80000000u) : ~(int)u;
    return __int_as_float(b);
}

// ---------------- prep: features + row norms + clears, one kernel ----------------
__global__ __launch_bounds__(256) void featrsq_kernel(const float* __restrict__ outp,
                                                      const float* __restrict__ targ) {
    int gid = blockIdx.x * blockDim.x + threadIdx.x;
    if (gid < NB * RP) { g_dmin[gid] = 0xFFFFFFFFu; g_rowsum[gid] = 0.0f; }
    if (gid < NB) g_acc[gid] = 0.0f;

    int gw = gid >> 5;
    int l  = threadIdx.x & 31;
    if (gw >= 2 * NB * RP) return;
    int row   = gw % RP;
    int n     = (gw / RP) % NB;
    int which = gw / (RP * NB);

    __nv_bfloat16* dst = g_hi + (size_t)gw * KP;
    const float* src = which ? targ : outp;
    int y = row / HF, x = row - y * HF;
    bool valid = (row < P);

    float sum = 0.0f;
    #pragma unroll
    for (int k = l; k < KP; k += 32) {
        float v = 0.0f;
        if (valid) {
            if (k < 75) {
                int c = k / 25, t = k - c * 25, dy = t / 5, dx = t - dy * 5;
                v = src[((n * 3 + c) * IN_H + y + dy) * IN_H + x + dx] - 0.5f;
            } else if (k == 75) v = CS * (float)y * (1.0f / 62.0f);
            else if (k == 76)   v = CS * (float)x * (1.0f / 62.0f);
        }
        dst[k] = __float2bfloat16(v);
        sum = fmaf(v, v, sum);
    }
    #pragma unroll
    for (int off = 16; off >= 1; off >>= 1)
        sum += __shfl_xor_sync(0xffffffffu, sum, off);
    if (l == 0) {
        if (which == 1 && row >= P) sum = 1e9f;   // T pad rows: huge dist -> exp underflows to 0
        g_r[gw] = sum;
    }
}

// ---------------- two-pass fused GEMM kernels ----------------
#define TS     176                 // smem row stride (bytes), ldmatrix conflict-free
#define TILE_B (128 * TS)          // 22528
#define SM_RT  0                   // 2 x 128 f
#define SM_RED 1024                // 128 u32: pass1 encoded min / pass2 float partial sums
#define SM_M   1536                // 128 f (pass2)
#define SM_B2  2048                // 128 f (pass2)
#define SM_AH  4096
#define SM_B0  (SM_AH + TILE_B)
#define SMEM_BYTES (SM_B0 + 2 * TILE_B)   // 71680 (70 KB); 2 CTAs/SM = 140 KB

__device__ __forceinline__ void load_B_async(uint32_t smB,
                                             const __nv_bfloat16* __restrict__ hi, int tid) {
    for (int t = tid; t < 1280; t += 256) {
        int row = t / 10, c = t - row * 10;
        cp16(smB + row * TS + c * 16, hi + row * KP + c * 8);
    }
}

template <int PASS>
__global__ __launch_bounds__(256, 2) void pass_kernel() {
    extern __shared__ char sm[];
    uint32_t smb = smem_u32(sm);
    int tid = threadIdx.x;
    int w = tid >> 5, l = tid & 31;
    int n  = blockIdx.z;
    int i0 = blockIdx.x * 128;
    int jh = blockIdx.y;
    int wm = w >> 1, wn = w & 1;        // 4 x 2 warp grid, warp tile 32 x 64

    float*    rT_s  = (float*)(sm + SM_RT);
    unsigned* red_s = (unsigned*)(sm + SM_RED);
    float*    sum_s = (float*)(sm + SM_RED);
    float*    m_s   = (float*)(sm + SM_M);
    float*    b_s   = (float*)(sm + SM_B2);

    // ---- load A_hi tile + per-pass row state ----
    const __nv_bfloat16* Ahi = g_hi + ((size_t)n * RP + i0) * KP;
    for (int t = tid; t < 1280; t += 256) {
        int row = t / 10, c = t - row * 10;
        *(uint4*)(sm + SM_AH + row * TS + c * 16) = *(const uint4*)(Ahi + row * KP + c * 8);
    }
    if (tid < 128) {
        if (PASS == 0) {
            red_s[tid] = 0xFFFFFFFFu;
        } else {
            sum_s[tid] = 0.0f;
            float smin = fdec(g_dmin[n * RP + i0 + tid]);
            float dmin = g_r[n * RP + i0 + tid] + smin;   // first half of g_r = rI
            float m = -L2E / (0.5f * (dmin + 1e-5f));
            m_s[tid] = m;
            b_s[tid] = -smin * m;
        }
    }
    __syncthreads();

    // ---- per-lane geometry ----
    int qr = l >> 2;
    int qc = (l & 3) * 2;
    int lrow = (l & 7) + ((l >> 3) & 1) * 8;
    int lcol = (l >> 4) * 16;
    int aoff = (wm * 32 + lrow) * TS + lcol;
    int boff = (wn * 64 + lrow) * TS + lcol;

    // ---- hoist A fragments into registers (invariant over the whole j loop) ----
    uint32_t AH[5][2][4];
    #pragma unroll
    for (int kk = 0; kk < 5; ++kk) {
        ldsm4(AH[kk][0], smb + SM_AH + aoff + kk * 32);
        ldsm4(AH[kk][1], smb + SM_AH + aoff + 16 * TS + kk * 32);
    }

    const __nv_bfloat16* Bhi0 = g_hi + ((size_t)(NB + n) * RP + jh * (NJT * 128)) * KP;
    const float* rTg = g_r + (NB + n) * RP + jh * (NJT * 128);

    float rmin[2][2] = {{1e30f, 1e30f}, {1e30f, 1e30f}};
    float rsum[2][2] = {{0.f, 0.f}, {0.f, 0.f}};
    float mrow[2][2], brow[2][2];
    if (PASS == 1) {
        #pragma unroll
        for (int mt = 0; mt < 2; ++mt)
            #pragma unroll
            for (int h = 0; h < 2; ++h) {
                int row = wm * 32 + mt * 16 + h * 8 + qr;
                mrow[mt][h] = m_s[row];
                brow[mt][h] = b_s[row];
            }
    }

    // preload j=0
    load_B_async(smb + SM_B0, Bhi0, tid);
    CP_COMMIT();
    if (tid < 128) rT_s[tid] = rTg[tid];

    for (int j = 0; j < NJT; ++j) {
        int cur = j & 1;
        CP_WAIT0();
        __syncthreads();               // B[cur] ready; everyone done reading B[cur^1]

        if (j + 1 < NJT) {
            load_B_async(smb + SM_B0 + (cur ^ 1) * TILE_B,
                         Bhi0 + (size_t)(j + 1) * 128 * KP, tid);
            CP_COMMIT();
            if (tid < 128) rT_s[(cur ^ 1) * 128 + tid] = rTg[(j + 1) * 128 + tid];
        }

        uint32_t Bcur = smb + SM_B0 + cur * TILE_B;

        // ---- f-outer / kk-inner: 16 B-columns at a time, small acc, hoisted A ----
        #pragma unroll
        for (int f = 0; f < 4; ++f) {
            float acc[2][2][4];        // [mt][ntl][quad]
            #pragma unroll
            for (int mt = 0; mt < 2; ++mt)
                #pragma unroll
                for (int ntl = 0; ntl < 2; ++ntl)
                    #pragma unroll
                    for (int q = 0; q < 4; ++q) acc[mt][ntl][q] = 0.0f;

            #pragma unroll
            for (int kk = 0; kk < 5; ++kk) {
                uint32_t BF[4];
                ldsm4(BF, Bcur + boff + f * 16 * TS + kk * 32);
                mma16816(acc[0][0], AH[kk][0], BF[0], BF[2]);
                mma16816(acc[0][1], AH[kk][0], BF[1], BF[3]);
                mma16816(acc[1][0], AH[kk][1], BF[0], BF[2]);
                mma16816(acc[1][1], AH[kk][1], BF[1], BF[3]);
            }

            // epilogue for columns [wn*64 + f*16, +16)
            #pragma unroll
            for (int ntl = 0; ntl < 2; ++ntl) {
                int nt = 2 * f + ntl;
                float2 rtp = *(const float2*)&rT_s[cur * 128 + wn * 64 + nt * 8 + qc];
                #pragma unroll
                for (int mt = 0; mt < 2; ++mt)
                    #pragma unroll
                    for (int h = 0; h < 2; ++h) {
                        float s0 = fmaf(-2.0f, acc[mt][ntl][2 * h],     rtp.x);
                        float s1 = fmaf(-2.0f, acc[mt][ntl][2 * h + 1], rtp.y);
                        if (PASS == 0) {
                            rmin[mt][h] = fminf(rmin[mt][h], fminf(s0, s1));
                        } else {
                            float a0 = fmaf(s0, mrow[mt][h], brow[mt][h]);
                            float a1 = fmaf(s1, mrow[mt][h], brow[mt][h]);
                            uint32_t e = ex2_f16x2(pack_f16x2(a0, a1));
                            float2 ef = __half22float2(*(__half2*)&e);
                            rsum[mt][h] += ef.x + ef.y;
                        }
                    }
            }
        }
    }

    // ---- per-row reductions: quad -> shared -> global ----
    if (PASS == 0) {
        #pragma unroll
        for (int mt = 0; mt < 2; ++mt)
            #pragma unroll
            for (int h = 0; h < 2; ++h) {
                float v = rmin[mt][h];
                v = fminf(v, __shfl_xor_sync(0xffffffffu, v, 1));
                v = fminf(v, __shfl_xor_sync(0xffffffffu, v, 2));
                if ((l & 3) == 0)
                    atomicMin(&red_s[wm * 32 + mt * 16 + qr + h * 8], fenc(v));
            }
        __syncthreads();
        if (tid < 128) atomicMin(&g_dmin[n * RP + i0 + tid], red_s[tid]);
    } else {
        #pragma unroll
        for (int mt = 0; mt < 2; ++mt)
            #pragma unroll
            for (int h = 0; h < 2; ++h) {
                float v = rsum[mt][h];
                v += __shfl_xor_sync(0xffffffffu, v, 1);
                v += __shfl_xor_sync(0xffffffffu, v, 2);
                if ((l & 3) == 0)
                    atomicAdd(&sum_s[wm * 32 + mt * 16 + qr + h * 8], v);
            }
        __syncthreads();
        if (tid < 128) atomicAdd(&g_rowsum[n * RP + i0 + tid], sum_s[tid]);
    }
}

// ---------------- finalize: per-image sum of k_max (parallel, rcp.approx) ----------------
__global__ __launch_bounds__(256) void finalize_kernel() {
    int n = blockIdx.y;
    int i = blockIdx.x * 256 + threadIdx.x;
    float s = (i < P) ? rcpf(g_rowsum[n * RP + i]) : 0.0f;
    #pragma unroll
    for (int off = 16; off >= 1; off >>= 1)
        s += __shfl_xor_sync(0xffffffffu, s, off);
    __shared__ float red[8];
    if ((threadIdx.x & 31) == 0) red[threadIdx.x >> 5] = s;
    __syncthreads();
    if (threadIdx.x == 0) {
        float t = 0.0f;
        #pragma unroll
        for (int q = 0; q < 8; ++q) t += red[q];
        atomicAdd(&g_acc[n], t);
    }
}

__global__ void final_kernel(float* out) {
    float L = 0.0f;
    #pragma unroll
    for (int n = 0; n < NB; ++n)
        L += -logf(g_acc[n] * (1.0f / (float)P));
    out[0] = L;
}

// ---------------- launch ----------------
extern "C" void kernel_launch(void* const* d_in, const int* in_sizes, int n_in,
                              void* d_out, int out_size) {
    const float* outp = (const float*)d_in[0];
    const float* targ = (const float*)d_in[1];
    float* out = (float*)d_out;

    cudaFuncSetAttribute(pass_kernel<0>, cudaFuncAttributeMaxDynamicSharedMemorySize, SMEM_BYTES);
    cudaFuncSetAttribute(pass_kernel<1>, cudaFuncAttributeMaxDynamicSharedMemorySize, SMEM_BYTES);

    featrsq_kernel<<<(2 * NB * RP) / 8, 256>>>(outp, targ);
    dim3 g(NI, NJH, NB);
    pass_kernel<0><<<g, 256, SMEM_BYTES>>>();
    pass_kernel<1><<<g, 256, SMEM_BYTES>>>();
    finalize_kernel<<<dim3(16, NB), 256>>>();
    final_kernel<<<1, 1>>>(out);
}